// round 7
// baseline (speedup 1.0000x reference)
#include <cuda_runtime.h>
#include <cuda_bf16.h>
#include <mma.h>
#include <math.h>
#include <stdint.h>

using namespace nvcuda;

#define F_IN   128
#define G_HID  128
#define L_HID  64
#define G4     256
#define N_CLS  8
#define PP     4
#define LSEQ   16
#define D_PATH 129
#define KP     208    // padded K (129 x + 64 h + 15 zero), 13 x 16
#define NCHK   13
#define NMAX   20000
#define BMAX   (NMAX*PP)

// ---------------- scratch (static device globals) -----------------------------
__device__ float g_deg [NMAX];
__device__ float g_dinv[NMAX];
__device__ float g_xw  [NMAX*G_HID];
__device__ float g_g0  [NMAX*G_HID];
__device__ float g_hout[2*(size_t)BMAX*L_HID];
__device__ int   g_idx64;
__device__ __nv_bfloat16 g_Wbh[2][KP][G4];   // weights hi, [dir][k][gate]
__device__ __nv_bfloat16 g_Wbl[2][KP][G4];   // weights lo
__device__ float g_Bt[2*G4];

// ---------------- helpers ------------------------------------------------------
__device__ __forceinline__ float sigf(float x){ return __fdividef(1.f, 1.f + __expf(-x)); }
__device__ __forceinline__ float tanhfast(float x){ return 2.f*sigf(2.f*x) - 1.f; }
__device__ __forceinline__ uint32_t s2u(const void* p){
  uint32_t a;
  asm("{ .reg .u64 t; cvta.to.shared.u64 t, %1; cvt.u32.u64 %0, t; }" : "=r"(a) : "l"(p));
  return a;
}
__device__ __forceinline__ void cpa16(uint32_t d, const void* s){
  asm volatile("cp.async.cg.shared.global [%0], [%1], 16;" :: "r"(d), "l"(s));
}

// ---------------- edge-index dtype detection -----------------------------------
__global__ void k_detect(const long long* __restrict__ e, int E){
  if (blockIdx.x == 0 && threadIdx.x == 0){
    int ok = 1;
    #pragma unroll
    for (int i = 0; i < 8; i++){ long long v = e[i]; if (v < 0 || v >= NMAX) ok = 0; }
    g_idx64 = ok;
  }
}

// ---------------- GCN -----------------------------------------------------------
__global__ void k_deg_init(int n){
  int i = blockIdx.x*blockDim.x + threadIdx.x;
  if (i < n) g_deg[i] = 1.0f;
}
__global__ void k_deg_edges(const long long* __restrict__ e64, const int* __restrict__ e32,
                            const float* __restrict__ ew, int E){
  int e = blockIdx.x*blockDim.x + threadIdx.x;
  if (e < E){
    int dst = g_idx64 ? (int)e64[(size_t)E + e] : e32[(size_t)E + e];
    atomicAdd(&g_deg[dst], ew[e]);
  }
}
__global__ void k_dinv(int n){
  int i = blockIdx.x*blockDim.x + threadIdx.x;
  if (i < n){ float d = g_deg[i]; g_dinv[i] = d > 0.f ? rsqrtf(d) : 0.f; }
}
__global__ void k_xw(const float* __restrict__ X, const float* __restrict__ Wg, int n){
  __shared__ float xs[16][128];
  int j  = threadIdx.x;
  int r0 = blockIdx.x*16;
  #pragma unroll
  for (int r = 0; r < 16; r++){
    int row = r0 + r;
    xs[r][j] = (row < n) ? X[(size_t)row*F_IN + j] : 0.f;
  }
  __syncthreads();
  float acc[16];
  #pragma unroll
  for (int r = 0; r < 16; r++) acc[r] = 0.f;
  for (int k = 0; k < F_IN; k++){
    float w = Wg[(size_t)k*G_HID + j];
    #pragma unroll
    for (int r = 0; r < 16; r++) acc[r] = fmaf(xs[r][k], w, acc[r]);
  }
  #pragma unroll
  for (int r = 0; r < 16; r++){
    int row = r0 + r;
    if (row < n) g_xw[(size_t)row*G_HID + j] = acc[r];
  }
}
__global__ void k_g0init(int n){
  int idx = blockIdx.x*blockDim.x + threadIdx.x;
  if (idx < n*G_HID){
    int ni = idx >> 7;
    float d = g_dinv[ni];
    g_g0[idx] = d*d*g_xw[idx];
  }
}
__global__ void k_agg(const long long* __restrict__ e64, const int* __restrict__ e32,
                      const float* __restrict__ ew, int E){
  int e    = blockIdx.x*8 + (threadIdx.x >> 5);
  int lane = threadIdx.x & 31;
  if (e < E){
    int src, dst;
    if (g_idx64){ src = (int)e64[e]; dst = (int)e64[(size_t)E + e]; }
    else        { src = e32[e];      dst = e32[(size_t)E + e]; }
    float nrm = g_dinv[src]*ew[e]*g_dinv[dst];
    const float4* xr = (const float4*)(g_xw + (size_t)src*G_HID);
    float4 v = xr[lane];
    float* gp = g_g0 + (size_t)dst*G_HID + lane*4;
    asm volatile("red.add.v4.f32 [%0], {%1,%2,%3,%4};"
                 :: "l"(gp), "f"(nrm*v.x), "f"(nrm*v.y), "f"(nrm*v.z), "f"(nrm*v.w)
                 : "memory");
  }
}

// ---------------- weight prep: fp32 -> bf16 hi/lo, [dir][k 0..207][gate] --------
__global__ void k_wprep(const float* __restrict__ Wihf, const float* __restrict__ Whhf,
                        const float* __restrict__ bihf, const float* __restrict__ bhhf,
                        const float* __restrict__ Wihb, const float* __restrict__ Whhb,
                        const float* __restrict__ bihb, const float* __restrict__ bhhb){
  int idx = blockIdx.x*blockDim.x + threadIdx.x;
  if (idx < 2*KP*G4){
    int d   = idx / (KP*G4);
    int rem = idx - d*(KP*G4);
    int k = rem >> 8;
    int j = rem & 255;
    const float* Wih = d ? Wihb : Wihf;
    const float* Whh = d ? Whhb : Whhf;
    float v = 0.f;
    if (k < D_PATH)              v = Wih[(size_t)j*D_PATH + k];
    else if (k < D_PATH + L_HID) v = Whh[(size_t)j*L_HID + (k - D_PATH)];
    __nv_bfloat16 h = __float2bfloat16(v);
    g_Wbh[d][k][j] = h;
    g_Wbl[d][k][j] = __float2bfloat16(v - __bfloat162float(h));
  }
  if (idx < 2*G4){
    int d = idx >> 8, j = idx & 255;
    g_Bt[idx] = d ? (bihb[j] + bhhb[j]) : (bihf[j] + bhhf[j]);
  }
}

// ---------------- fused BiLSTM (WMMA bf16, split hi/lo, 3 products) -------------
// 512 thr = 16 warps (4x4 warp grid: 32 seqs x 64 gate cols per warp).
// Per step: G[128,256] = comb[128,208] @ W[208,256] via 13 K-chunks of 16,
// weights cp.async double-buffered; comb bf16 hi/lo aliased under fp32 gates.
// smem layout (bytes):
//   0      : gates fp32 [128][256]        (131072)  -- aliases combH/combL
//   0      : combH bf16 [128][208]        (53248)
//   53248  : combL bf16 [128][208]        (53248)
//   131072 : hs fp32 [128][64]            (32768)
//   163840 : cs fp32 [128][64]            (32768)
//   196608 : wbuf 2 x (H 8192 + L 8192)   (32768)
//   229376 : bias fp32 [256]              (1024)   -> total 230400
#define SM_HS   131072
#define SM_CS   163840
#define SM_WB   196608
#define SM_BS   229376
#define SM_TOT  230400

__global__ void __launch_bounds__(512,1) k_lstm(const float* __restrict__ Cin, int B){
  extern __shared__ char sm[];
  float*         gs    = (float*)sm;
  __nv_bfloat16* combH = (__nv_bfloat16*)sm;
  __nv_bfloat16* combL = (__nv_bfloat16*)(sm + 53248);
  float*         hs    = (float*)(sm + SM_HS);
  float*         cs    = (float*)(sm + SM_CS);
  float*         bsh   = (float*)(sm + SM_BS);
  const uint32_t wbA   = s2u(sm + SM_WB);

  const int tid = threadIdx.x, wid = tid >> 5;
  const int wr = wid >> 2, wc = wid & 3;
  const int dir = blockIdx.y;
  const int b0  = blockIdx.x * 128;
  const __nv_bfloat16* WH = &g_Wbh[dir][0][0];
  const __nv_bfloat16* WL = &g_Wbl[dir][0][0];

  for (int i = tid; i < 128*64; i += 512){ hs[i] = 0.f; cs[i] = 0.f; }
  if (tid < 256) bsh[tid] = g_Bt[dir*G4 + tid];
  __syncthreads();

  for (int step = 0; step < LSEQ; ++step){
    const int l = dir ? (LSEQ-1-step) : step;

    // prime weight chunk 0 into buf0 (flies during comb staging)
    {
      uint32_t dH = wbA + tid*16;
      cpa16(dH,        WH + tid*8);
      cpa16(dH + 8192, WL + tid*8);
      asm volatile("cp.async.commit_group;" ::: "memory");
    }

    // ---- stage comb: x (fp32->hi/lo), h, zero pads ----
    {
      const float* src = Cin + ((size_t)b0*LSEQ + l)*D_PATH;
      for (int i = tid; i < 128*D_PATH; i += 512){
        int r = i / D_PATH, c = i - r*D_PATH;
        float v = src[(size_t)r*(LSEQ*D_PATH) + c];
        __nv_bfloat16 h = __float2bfloat16(v);
        combH[r*KP + c] = h;
        combL[r*KP + c] = __float2bfloat16(v - __bfloat162float(h));
      }
      for (int i = tid; i < 128*64; i += 512){
        int r = i >> 6, u = i & 63;
        float v = hs[i];
        __nv_bfloat16 h = __float2bfloat16(v);
        combH[r*KP + D_PATH + u] = h;
        combL[r*KP + D_PATH + u] = __float2bfloat16(v - __bfloat162float(h));
      }
      __nv_bfloat16 z = __float2bfloat16(0.f);
      for (int i = tid; i < 128*16; i += 512){
        int r = i >> 4, c = i & 15;
        if (c < 15){ combH[r*KP + 193 + c] = z; combL[r*KP + 193 + c] = z; }
      }
    }
    __syncthreads();   // comb visible; prev-step buf users finished earlier

    wmma::fragment<wmma::accumulator,16,16,16,float> acc[2][4];
    #pragma unroll
    for (int i = 0; i < 2; i++)
      #pragma unroll
      for (int j = 0; j < 4; j++) wmma::fill_fragment(acc[i][j], 0.f);

    // ---- 13 K-chunks, cp.async double-buffered ----
    #pragma unroll 1
    for (int ch = 0; ch < NCHK; ch++){
      const int buf = ch & 1;
      if (ch < NCHK-1){
        uint32_t dH = wbA + (buf^1)*16384 + tid*16;
        cpa16(dH,        WH + (size_t)(ch+1)*16*256 + tid*8);
        cpa16(dH + 8192, WL + (size_t)(ch+1)*16*256 + tid*8);
        asm volatile("cp.async.commit_group;" ::: "memory");
        asm volatile("cp.async.wait_group 1;" ::: "memory");
      } else {
        asm volatile("cp.async.wait_group 0;" ::: "memory");
      }
      __syncthreads();

      const __nv_bfloat16* bufH = (const __nv_bfloat16*)(sm + SM_WB + buf*16384);
      const __nv_bfloat16* bufL = bufH + 4096;
      const int k0 = ch*16;

      wmma::fragment<wmma::matrix_a,16,16,16,__nv_bfloat16,wmma::row_major> aH0,aH1,aL0,aL1;
      wmma::load_matrix_sync(aH0, combH + (wr*32   )*KP + k0, KP);
      wmma::load_matrix_sync(aH1, combH + (wr*32+16)*KP + k0, KP);
      wmma::load_matrix_sync(aL0, combL + (wr*32   )*KP + k0, KP);
      wmma::load_matrix_sync(aL1, combL + (wr*32+16)*KP + k0, KP);
      #pragma unroll
      for (int j = 0; j < 4; j++){
        wmma::fragment<wmma::matrix_b,16,16,16,__nv_bfloat16,wmma::row_major> bH,bL;
        wmma::load_matrix_sync(bH, bufH + wc*64 + j*16, 256);
        wmma::load_matrix_sync(bL, bufL + wc*64 + j*16, 256);
        wmma::mma_sync(acc[0][j], aH0, bH, acc[0][j]);
        wmma::mma_sync(acc[1][j], aH1, bH, acc[1][j]);
        wmma::mma_sync(acc[0][j], aL0, bH, acc[0][j]);
        wmma::mma_sync(acc[1][j], aL1, bH, acc[1][j]);
        wmma::mma_sync(acc[0][j], aH0, bL, acc[0][j]);
        wmma::mma_sync(acc[1][j], aH1, bL, acc[1][j]);
      }
      __syncthreads();   // chunk consumed before its buffer is re-filled
    }

    // ---- gates to smem (overwrites comb alias; all comb reads done) ----
    #pragma unroll
    for (int i = 0; i < 2; i++)
      #pragma unroll
      for (int j = 0; j < 4; j++)
        wmma::store_matrix_sync(gs + (size_t)(wr*32 + i*16)*256 + wc*64 + j*16,
                                acc[i][j], 256, wmma::mem_row_major);
    __syncthreads();

    // ---- cell update (gate order i,f,g,o) ----
    {
      const int q = tid >> 6;      // 0..7
      const int u = tid & 63;
      #pragma unroll
      for (int r = 0; r < 16; r++){
        int seq = r*8 + q;
        float gi = gs[seq*G4 +       u] + bsh[u];
        float gf = gs[seq*G4 +  64 + u] + bsh[64 + u];
        float gg = gs[seq*G4 + 128 + u] + bsh[128 + u];
        float go = gs[seq*G4 + 192 + u] + bsh[192 + u];
        float c  = sigf(gf)*cs[seq*64 + u] + sigf(gi)*tanhfast(gg);
        cs[seq*64 + u] = c;
        hs[seq*64 + u] = sigf(go)*tanhfast(c);
      }
    }
    __syncthreads();
  }

  for (int i = tid; i < 128*64; i += 512){
    int r = i >> 6, u = i & 63;
    g_hout[(size_t)dir*B*L_HID + (size_t)(b0 + r)*L_HID + u] = hs[i];
  }
}

// ---------------- final fuse ------------------------------------------------------
__global__ void k_fuse(const float* __restrict__ bg, const float* __restrict__ Wf,
                       const float* __restrict__ bf, float* __restrict__ out,
                       int N, int B){
  __shared__ float v[256];
  int n = blockIdx.x;
  int t = threadIdx.x;
  float val;
  if (t < 128){
    val = g_g0[(size_t)n*G_HID + t] + bg[t];
    val = val > 0.f ? val : 0.f;
  } else if (t < 192){
    int u = t - 128;
    const float* hf = g_hout + (size_t)(n*PP)*L_HID + u;
    val = 0.25f*(hf[0] + hf[L_HID] + hf[2*L_HID] + hf[3*L_HID]);
  } else {
    int u = t - 192;
    const float* hb = g_hout + (size_t)B*L_HID + (size_t)(n*PP)*L_HID + u;
    val = 0.25f*(hb[0] + hb[L_HID] + hb[2*L_HID] + hb[3*L_HID]);
  }
  v[t] = val;
  __syncthreads();
  int c = t >> 5, lane = t & 31;
  float s = 0.f;
  for (int k = lane; k < 256; k += 32) s += v[k]*Wf[(size_t)k*N_CLS + c];
  #pragma unroll
  for (int off = 16; off; off >>= 1) s += __shfl_down_sync(0xffffffffu, s, off);
  if (lane == 0) out[(size_t)n*N_CLS + c] = s + bf[c];
}

// ---------------- launch ------------------------------------------------------------
// k_lstm is the 6th launch (slot 5) so ncu -s 5 -c 1 profiles it.
extern "C" void kernel_launch(void* const* d_in, const int* in_sizes, int n_in,
                              void* d_out, int out_size){
  const float*     X    = (const float*)d_in[0];
  const long long* EI64 = (const long long*)d_in[1];
  const int*       EI32 = (const int*)d_in[1];
  const float*     EW   = (const float*)d_in[2];
  const float*     C    = (const float*)d_in[3];
  const float*     Wg   = (const float*)d_in[4];
  const float*     bg   = (const float*)d_in[5];
  const float*     Wihf = (const float*)d_in[6];
  const float*     Whhf = (const float*)d_in[7];
  const float*     bihf = (const float*)d_in[8];
  const float*     bhhf = (const float*)d_in[9];
  const float*     Wihb = (const float*)d_in[10];
  const float*     Whhb = (const float*)d_in[11];
  const float*     bihb = (const float*)d_in[12];
  const float*     bhhb = (const float*)d_in[13];
  const float*     Wf   = (const float*)d_in[14];
  const float*     bf   = (const float*)d_in[15];
  float* out = (float*)d_out;

  const int N = in_sizes[0] / F_IN;
  const int E = in_sizes[1] / 2;
  const int B = N * PP;

  cudaFuncSetAttribute(k_lstm, cudaFuncAttributeMaxDynamicSharedMemorySize, SM_TOT);

  k_detect   <<<1, 32>>>(EI64, E);                                        // 0
  k_deg_init <<<(N + 255)/256, 256>>>(N);                                 // 1
  k_deg_edges<<<(E + 255)/256, 256>>>(EI64, EI32, EW, E);                 // 2
  k_dinv     <<<(N + 255)/256, 256>>>(N);                                 // 3
  k_wprep    <<<(2*KP*G4 + 255)/256, 256>>>(Wihf, Whhf, bihf, bhhf,       // 4
                                            Wihb, Whhb, bihb, bhhb);
  dim3 lgrid(B/128, 2);
  k_lstm     <<<lgrid, 512, SM_TOT>>>(C, B);                              // 5 <- profiled
  k_xw       <<<(N + 15)/16, 128>>>(X, Wg, N);                            // 6
  k_g0init   <<<(N*G_HID + 255)/256, 256>>>(N);                           // 7
  k_agg      <<<(E + 7)/8, 256>>>(EI64, EI32, EW, E);                     // 8
  k_fuse     <<<N, 256>>>(bg, Wf, bf, out, N, B);                         // 9
}